// round 14
// baseline (speedup 1.0000x reference)
#include <cuda_runtime.h>
#include <cuda_fp16.h>
#include <cstdint>
#include <math.h>

// Problem constants
#define NB    16
#define CDIM  512
#define TDIM  256
#define VV    25
#define HEADS 8
#define HD    64
#define MCOL  6400
#define QROWS 1536

// Scratch (__device__ globals per allocation-free rule)
__device__ float  g_qkv[(size_t)NB * QROWS * MCOL];   // QKV output (fp32)
__device__ __half g_att[(size_t)NB * CDIM * MCOL];    // attn output (fp16)
__device__ __half g_x16[(size_t)NB * CDIM * MCOL];    // x -> fp16
__device__ __half g_wq16[QROWS * CDIM];               // w_qkv -> fp16
__device__ __half g_wp16[CDIM * CDIM];                // w_proj -> fp16

// ---------------------------------------------------------------------------
__device__ __forceinline__ uint32_t smem_u32(const void* p) {
    uint32_t a;
    asm("{ .reg .u64 t; cvta.to.shared.u64 t, %1; cvt.u32.u64 %0, t; }" : "=r"(a) : "l"(p));
    return a;
}
__device__ __forceinline__ void mma_f16(float* c, const uint32_t* a, const uint32_t* b) {
    asm volatile(
        "mma.sync.aligned.m16n8k16.row.col.f32.f16.f16.f32 "
        "{%0,%1,%2,%3}, {%4,%5,%6,%7}, {%8,%9}, {%0,%1,%2,%3};"
        : "+f"(c[0]), "+f"(c[1]), "+f"(c[2]), "+f"(c[3])
        : "r"(a[0]), "r"(a[1]), "r"(a[2]), "r"(a[3]), "r"(b[0]), "r"(b[1]));
}
#define CP16(dst, src) \
    asm volatile("cp.async.cg.shared.global [%0], [%1], 16;" :: "r"(dst), "l"(src))
#define CP_COMMIT() asm volatile("cp.async.commit_group;" ::: "memory")

// ---------------------------------------------------------------------------
// fp16 GEMM: C_f32[M,N] = A_f16[M,512] @ B_f16[512,N], row-major.
// CTA 128x128, 4 warps (2m x 2n) of 64x64, 128 threads, 2 CTAs/SM.
// Fragment-crossbar per MMA: 4/nt + 2/mt = 1.0 cyc (was 1.5 at 64x32).
// A smem: [m][64B] rows, chunk-xor swizzle (c ^= (m>>1)&3) -> conflict-free.
// B smem: [k][272B] rows: addr16 = 17k+c -> conflict-free (incl. x4.trans).
// ---------------------------------------------------------------------------
#define BMT 128
#define BNT 128
#define KT  32
#define NSTAGE 4
#define A_STB  (128 * 64)               // 8192
#define BROW   272
#define B_STB  (32 * BROW)              // 8704
#define B_OFF  (NSTAGE * A_STB)         // 32768
#define SMEM_G (B_OFF + NSTAGE * B_STB) // 67584

__global__ __launch_bounds__(128, 2)
void h16_gemm(const __half* __restrict__ A, const __half* __restrict__ B,
              float* __restrict__ C, int Nld, long sB, long sC)
{
    extern __shared__ char sm[];
    const uint32_t sbase = smem_u32(sm);
    B += (long)blockIdx.z * sB;
    C += (long)blockIdx.z * sC;
    const int bm = blockIdx.y * BMT;
    const int bn = blockIdx.x * BNT;

    const int tid  = threadIdx.x;
    const int wid  = tid >> 5, lane = tid & 31;
    const int g    = lane >> 2, tg = lane & 3;
    const int wm   = (wid & 1) * 64, wn = (wid >> 1) * 64;

    // A staging: thread -> row tid (0..127), 4 chunks of 16B, xor-swizzled
    const __half* Ag = A + (long)(bm + tid) * CDIM;
    const uint32_t am_sw = (uint32_t)((tid >> 1) & 3);
    // B staging: 4 threads per k-row, 4 chunks each
    const int bk = tid >> 2, bc = (tid & 3) * 4;
    const __half* Bg = B + (long)bk * Nld + bn + bc * 8;
    const uint32_t b_soff = (uint32_t)(bk * BROW + bc * 16);

    // ldmatrix lane selectors
    const int arow  = lane & 15;                             // m row in 16-tile
    const int achk  = lane >> 4;                             // k-chunk in k16
    const int bkrow = (lane & 7) + ((lane >> 3) & 1) * 8;    // k row in k16
    const int bcoff = ((lane >> 4) & 1) * 8;                 // col group for x4

    float acc[4][8][4];
    #pragma unroll
    for (int i = 0; i < 4; i++)
        #pragma unroll
        for (int j = 0; j < 8; j++)
            #pragma unroll
            for (int q = 0; q < 4; q++) acc[i][j][q] = 0.f;

    auto issue = [&](int s) {
        const int st = s & (NSTAGE - 1);
        const uint32_t ab = sbase + st * A_STB + tid * 64;
        const __half* ag = Ag + s * KT;
        #pragma unroll
        for (int j = 0; j < 4; j++)
            CP16(ab + (((uint32_t)j ^ am_sw) << 4), ag + j * 8);
        const uint32_t bb = sbase + B_OFF + st * B_STB + b_soff;
        const __half* bg = Bg + (long)s * KT * Nld;
        #pragma unroll
        for (int j = 0; j < 4; j++)
            CP16(bb + j * 16, bg + j * 8);
    };

    issue(0); CP_COMMIT();
    issue(1); CP_COMMIT();
    issue(2); CP_COMMIT();

    const int NIT = CDIM / KT;   // 16
    for (int s = 0; s < NIT; s++) {
        asm volatile("cp.async.wait_group 2;" ::: "memory");
        __syncthreads();
        if (s + 3 < NIT) issue(s + 3);
        CP_COMMIT();

        const int st = s & (NSTAGE - 1);
        const uint32_t ab = sbase + st * A_STB;
        const uint32_t bb = sbase + B_OFF + st * B_STB;
        #pragma unroll
        for (int ks = 0; ks < 2; ks++) {
            uint32_t af[4][4];
            #pragma unroll
            for (int mt = 0; mt < 4; mt++) {
                const int ml = wm + mt * 16 + arow;
                const uint32_t ad = ab + ml * 64 +
                    (((uint32_t)(ks * 2 + achk)) ^ ((uint32_t)((ml >> 1) & 3))) * 16;
                asm volatile("ldmatrix.sync.aligned.m8n8.x4.shared.b16 {%0,%1,%2,%3}, [%4];"
                    : "=r"(af[mt][0]), "=r"(af[mt][1]), "=r"(af[mt][2]), "=r"(af[mt][3])
                    : "r"(ad));
            }
            uint32_t bf[8][2];
            #pragma unroll
            for (int ntp = 0; ntp < 4; ntp++) {
                const uint32_t bd = bb + (ks * 16 + bkrow) * BROW +
                                    (wn + ntp * 16 + bcoff) * 2;
                asm volatile("ldmatrix.sync.aligned.m8n8.x4.trans.shared.b16 {%0,%1,%2,%3}, [%4];"
                    : "=r"(bf[2 * ntp][0]), "=r"(bf[2 * ntp][1]),
                      "=r"(bf[2 * ntp + 1][0]), "=r"(bf[2 * ntp + 1][1])
                    : "r"(bd));
            }
            #pragma unroll
            for (int mt = 0; mt < 4; mt++)
                #pragma unroll
                for (int nt = 0; nt < 8; nt++)
                    mma_f16(acc[mt][nt], af[mt], bf[nt]);
        }
    }

    // Epilogue
    #pragma unroll
    for (int mt = 0; mt < 4; mt++) {
        #pragma unroll
        for (int nt = 0; nt < 8; nt++) {
            const long r0 = bm + wm + mt * 16 + g;
            const int  cc = bn + wn + nt * 8 + 2 * tg;
            *(float2*)(C + r0 * Nld + cc)       = make_float2(acc[mt][nt][0], acc[mt][nt][1]);
            *(float2*)(C + (r0 + 8) * Nld + cc) = make_float2(acc[mt][nt][2], acc[mt][nt][3]);
        }
    }
}

// ---------------------------------------------------------------------------
// fp32 -> fp16 convert pass
// ---------------------------------------------------------------------------
__global__ void tohalf_k(const float4* __restrict__ in, __half2* __restrict__ o, long n4)
{
    long i = (long)blockIdx.x * blockDim.x + threadIdx.x;
    const long stride = (long)gridDim.x * blockDim.x;
    for (; i < n4; i += stride) {
        float4 v = in[i];
        o[2 * i]     = __floats2half2_rn(v.x, v.y);
        o[2 * i + 1] = __floats2half2_rn(v.z, v.w);
    }
}

// ---------------------------------------------------------------------------
// Attention middle: one CTA per (n,t), softmax over HEADS axis.
// smem floats: QV [512][25] at 0 | K padded [512][26] at AS_OFF | fp16 probs.
// Total 114448 B -> 2 CTAs/SM.
// ---------------------------------------------------------------------------
#define KPAD    26
#define AS_OFF  (512 * VV)                  // 12800: K starts here
#define PR_OFF  (AS_OFF + 512 * KPAD)       // 26112: fp16 probs start (float idx)
#define ATTN_SMEM (PR_OFF * 4 + HEADS * 625 * 2)   // 114448

__global__ __launch_bounds__(256, 2)
void attn_kernel(const float* __restrict__ qkv, __half* __restrict__ att)
{
    extern __shared__ float smem[];
    float*  qv  = smem;                       // Q, later V: [512][25]
    float*  ks  = smem + AS_OFF;              // K: [512][26] (col 25 = pad)
    __half* pr  = (__half*)(smem + PR_OFF);   // logits/probs [8][625]

    const int b  = blockIdx.x;
    const int n  = b >> 8;
    const int ti = b & 255;
    const float* src = qkv + (long)n * QROWS * MCOL + ti * VV;
    const int tid = threadIdx.x;

    // Stage Q (rows 0-511) and K (rows 512-1023): warp -> row, lanes 0-24
    {
        const float* srcK = src + (long)512 * MCOL;
        for (int idx = tid; idx < 512 * 32; idx += 256) {
            const int r = idx >> 5, l = idx & 31;
            if (l < VV) {
                qv[r * VV + l]   = src [(long)r * MCOL + l];
                ks[r * KPAD + l] = srcK[(long)r * MCOL + l];
            }
        }
    }
    __syncthreads();

    const int h = tid >> 5;
    const int i = tid & 31;

    // Phase 1: logits[h][i][j] = 0.125 * sum_d q[d][i]*k[d][j]
    if (i < VV) {
        const float* qcol = qv + (h * HD) * VV + i;   // stride VV per d
        const float* kb   = ks + (h * HD) * KPAD;
        float acc[VV];
        #pragma unroll
        for (int j = 0; j < VV; j++) acc[j] = 0.f;
        #pragma unroll 4
        for (int d = 0; d < HD; d++) {
            const float qd = qcol[d * VV];
            const float2* row = (const float2*)(kb + d * KPAD);
            #pragma unroll
            for (int jp = 0; jp < 12; jp++) {
                const float2 kv = row[jp];
                acc[2 * jp]     += qd * kv.x;
                acc[2 * jp + 1] += qd * kv.y;
            }
            acc[24] += qd * kb[d * KPAD + 24];
        }
        __half* prr = pr + h * 625 + i * VV;
        #pragma unroll
        for (int j = 0; j < VV; j++)
            prr[j] = __float2half_rn(acc[j] * 0.125f);
    }
    __syncthreads();

    // Phase 2: softmax over heads; then overwrite Q region with V
    for (int p = tid; p < 625; p += 256) {
        float v[HEADS];
        #pragma unroll
        for (int hh = 0; hh < HEADS; hh++) v[hh] = __half2float(pr[hh * 625 + p]);
        float m = v[0];
        #pragma unroll
        for (int hh = 1; hh < HEADS; hh++) m = fmaxf(m, v[hh]);
        float ssum = 0.f;
        #pragma unroll
        for (int hh = 0; hh < HEADS; hh++) { v[hh] = expf(v[hh] - m); ssum += v[hh]; }
        float inv = 1.f / ssum;
        #pragma unroll
        for (int hh = 0; hh < HEADS; hh++) pr[hh * 625 + p] = __float2half_rn(v[hh] * inv);
    }
    {
        const float* srcV = src + (long)1024 * MCOL;
        for (int idx = tid; idx < 512 * 32; idx += 256) {
            const int r = idx >> 5, l = idx & 31;
            if (l < VV)
                qv[r * VV + l] = srcV[(long)r * MCOL + l];
        }
    }
    __syncthreads();

    // Phase 3: out[h][i][d] = sum_j probs[h][i][j] * v[h][j][d]
    if (i < VV) {
        float o[HD];
        #pragma unroll
        for (int d = 0; d < HD; d++) o[d] = 0.f;
        const float* vb = qv + (h * HD) * VV;
        const __half* ar = pr + h * 625 + i * VV;
        for (int j = 0; j < VV; j++) {
            const float a = __half2float(ar[j]);
            #pragma unroll
            for (int d = 0; d < HD; d++) o[d] += a * vb[d * VV + j];
        }
        __half* dst = att + (long)n * CDIM * MCOL + (long)(h * HD) * MCOL + ti * VV + i;
        #pragma unroll
        for (int d = 0; d < HD; d++)
            dst[(long)d * MCOL] = __float2half_rn(o[d]);
    }
}

// ---------------------------------------------------------------------------
extern "C" void kernel_launch(void* const* d_in, const int* in_sizes, int n_in,
                              void* d_out, int out_size)
{
    const float* x     = (const float*)d_in[0];   // [16,512,256,25]
    const float* wqkv  = (const float*)d_in[1];   // [1536,512]
    const float* wproj = (const float*)d_in[2];   // [512,512]
    float* out = (float*)d_out;

    float  *qkv;
    __half *att, *x16, *wq16, *wp16;
    cudaGetSymbolAddress((void**)&qkv,  g_qkv);
    cudaGetSymbolAddress((void**)&att,  g_att);
    cudaGetSymbolAddress((void**)&x16,  g_x16);
    cudaGetSymbolAddress((void**)&wq16, g_wq16);
    cudaGetSymbolAddress((void**)&wp16, g_wp16);

    cudaFuncSetAttribute((const void*)h16_gemm,
                         cudaFuncAttributeMaxDynamicSharedMemorySize, SMEM_G);
    cudaFuncSetAttribute((const void*)attn_kernel,
                         cudaFuncAttributeMaxDynamicSharedMemorySize, ATTN_SMEM);

    // fp16 convert passes
    tohalf_k<<<4096, 256>>>((const float4*)x,     (__half2*)x16,  (long)NB * CDIM * MCOL / 4);
    tohalf_k<<<512,  256>>>((const float4*)wqkv,  (__half2*)wq16, (long)QROWS * CDIM / 4);
    tohalf_k<<<512,  256>>>((const float4*)wproj, (__half2*)wp16, (long)CDIM * CDIM / 4);

    // QKV: per-n [1536,6400] = W_qkv[1536,512] @ X_n[512,6400]
    h16_gemm<<<dim3(MCOL / BNT, QROWS / BMT, NB), 128, SMEM_G>>>(
        wq16, x16, qkv, MCOL, (long)CDIM * MCOL, (long)QROWS * MCOL);

    attn_kernel<<<dim3(NB * TDIM), 256, ATTN_SMEM>>>(qkv, att);

    // Proj: per-n [512,6400] = W_proj[512,512] @ O_n[512,6400]
    h16_gemm<<<dim3(MCOL / BNT, CDIM / BMT, NB), 128, SMEM_G>>>(
        wp16, att, out, MCOL, (long)CDIM * MCOL, (long)CDIM * MCOL);
}

// round 15
// speedup vs baseline: 1.4078x; 1.4078x over previous
#include <cuda_runtime.h>
#include <cuda_fp16.h>
#include <cstdint>
#include <math.h>

// Problem constants
#define NB    16
#define CDIM  512
#define TDIM  256
#define VV    25
#define HEADS 8
#define HD    64
#define MCOL  6400
#define QROWS 1536

// Scratch (__device__ globals per allocation-free rule)
__device__ float  g_qkv[(size_t)NB * QROWS * MCOL];   // QKV output (fp32)
__device__ __half g_att[(size_t)NB * CDIM * MCOL];    // attn output (fp16)
__device__ __half g_x16[(size_t)NB * CDIM * MCOL];    // x -> fp16
__device__ __half g_wq16[QROWS * CDIM];               // w_qkv -> fp16
__device__ __half g_wp16[CDIM * CDIM];                // w_proj -> fp16

// ---------------------------------------------------------------------------
__device__ __forceinline__ uint32_t smem_u32(const void* p) {
    uint32_t a;
    asm("{ .reg .u64 t; cvta.to.shared.u64 t, %1; cvt.u32.u64 %0, t; }" : "=r"(a) : "l"(p));
    return a;
}
__device__ __forceinline__ void mma_f16(float* c, const uint32_t* a, const uint32_t* b) {
    asm volatile(
        "mma.sync.aligned.m16n8k16.row.col.f32.f16.f16.f32 "
        "{%0,%1,%2,%3}, {%4,%5,%6,%7}, {%8,%9}, {%0,%1,%2,%3};"
        : "+f"(c[0]), "+f"(c[1]), "+f"(c[2]), "+f"(c[3])
        : "r"(a[0]), "r"(a[1]), "r"(a[2]), "r"(a[3]), "r"(b[0]), "r"(b[1]));
}
#define CP16(dst, src) \
    asm volatile("cp.async.cg.shared.global [%0], [%1], 16;" :: "r"(dst), "l"(src))
#define CP_COMMIT() asm volatile("cp.async.commit_group;" ::: "memory")
#define LDMX4(r, ad) \
    asm volatile("ldmatrix.sync.aligned.m8n8.x4.shared.b16 {%0,%1,%2,%3}, [%4];" \
        : "=r"((r)[0]), "=r"((r)[1]), "=r"((r)[2]), "=r"((r)[3]) : "r"(ad))
#define LDMX4T(r0, r1, r2, r3, ad) \
    asm volatile("ldmatrix.sync.aligned.m8n8.x4.trans.shared.b16 {%0,%1,%2,%3}, [%4];" \
        : "=r"(r0), "=r"(r1), "=r"(r2), "=r"(r3) : "r"(ad))

// ---------------------------------------------------------------------------
// fp16 GEMM (R13 config, proven 455us): CTA 128x128, 8 warps (2m x 4n) 64x32,
// KT=32, 4-stage cp.async, 2 CTAs/SM.
// ---------------------------------------------------------------------------
#define BMT 128
#define BNT 128
#define KT  32
#define NSTAGE 4
#define A_STB  (128 * 64)
#define BROW   272
#define B_STB  (32 * BROW)
#define B_OFF  (NSTAGE * A_STB)
#define SMEM_G (B_OFF + NSTAGE * B_STB)   // 67584

__global__ __launch_bounds__(256, 2)
void h16_gemm(const __half* __restrict__ A, const __half* __restrict__ B,
              float* __restrict__ C, int Nld, long sB, long sC)
{
    extern __shared__ char sm[];
    const uint32_t sbase = smem_u32(sm);
    B += (long)blockIdx.z * sB;
    C += (long)blockIdx.z * sC;
    const int bm = blockIdx.y * BMT;
    const int bn = blockIdx.x * BNT;

    const int tid  = threadIdx.x;
    const int wid  = tid >> 5, lane = tid & 31;
    const int g    = lane >> 2, tg = lane & 3;
    const int wm   = (wid & 1) * 64, wn = (wid >> 1) * 32;

    const int am = tid >> 1, ac = tid & 1;
    const __half* Ag = A + (long)(bm + am) * CDIM + ac * 16;
    const uint32_t am_sw = (uint32_t)((am >> 1) & 3);
    const int bk = tid >> 3, bc = tid & 7;
    const __half* Bg = B + (long)bk * Nld + bn + bc * 8;
    const uint32_t b_soff = (uint32_t)(bk * BROW + bc * 16);

    const int arow  = lane & 15;
    const int achk  = lane >> 4;
    const int bkrow = (lane & 7) + ((lane >> 3) & 1) * 8;
    const int bcoff = ((lane >> 4) & 1) * 8;

    float acc[4][4][4];
    #pragma unroll
    for (int i = 0; i < 4; i++)
        #pragma unroll
        for (int j = 0; j < 4; j++)
            #pragma unroll
            for (int q = 0; q < 4; q++) acc[i][j][q] = 0.f;

    auto issue = [&](int s) {
        const int st = s & (NSTAGE - 1);
        const uint32_t ab = sbase + st * A_STB + am * 64;
        const __half* ag = Ag + s * KT;
        #pragma unroll
        for (int j = 0; j < 2; j++)
            CP16(ab + (((uint32_t)(2 * ac + j)) ^ am_sw) * 16, ag + j * 8);
        const uint32_t bb = sbase + B_OFF + st * B_STB + b_soff;
        const __half* bg = Bg + (long)s * KT * Nld;
        CP16(bb, bg);
        CP16(bb + 128, bg + 64);
    };

    issue(0); CP_COMMIT();
    issue(1); CP_COMMIT();
    issue(2); CP_COMMIT();

    const int NIT = CDIM / KT;
    for (int s = 0; s < NIT; s++) {
        asm volatile("cp.async.wait_group 2;" ::: "memory");
        __syncthreads();
        if (s + 3 < NIT) issue(s + 3);
        CP_COMMIT();

        const int st = s & (NSTAGE - 1);
        const uint32_t ab = sbase + st * A_STB;
        const uint32_t bb = sbase + B_OFF + st * B_STB;
        #pragma unroll
        for (int ks = 0; ks < 2; ks++) {
            uint32_t af[4][4];
            #pragma unroll
            for (int mt = 0; mt < 4; mt++) {
                const int ml = wm + mt * 16 + arow;
                const uint32_t ad = ab + ml * 64 +
                    (((uint32_t)(ks * 2 + achk)) ^ ((uint32_t)((ml >> 1) & 3))) * 16;
                LDMX4(af[mt], ad);
            }
            uint32_t bf[4][2];
            #pragma unroll
            for (int ntp = 0; ntp < 2; ntp++) {
                const uint32_t bd = bb + (ks * 16 + bkrow) * BROW +
                                    (wn + ntp * 16 + bcoff) * 2;
                LDMX4T(bf[2 * ntp][0], bf[2 * ntp][1],
                       bf[2 * ntp + 1][0], bf[2 * ntp + 1][1], bd);
            }
            #pragma unroll
            for (int mt = 0; mt < 4; mt++)
                #pragma unroll
                for (int nt = 0; nt < 4; nt++)
                    mma_f16(acc[mt][nt], af[mt], bf[nt]);
        }
    }

    #pragma unroll
    for (int mt = 0; mt < 4; mt++) {
        #pragma unroll
        for (int nt = 0; nt < 4; nt++) {
            const long r0 = bm + wm + mt * 16 + g;
            const int  cc = bn + wn + nt * 8 + 2 * tg;
            *(float2*)(C + r0 * Nld + cc)       = make_float2(acc[mt][nt][0], acc[mt][nt][1]);
            *(float2*)(C + (r0 + 8) * Nld + cc) = make_float2(acc[mt][nt][2], acc[mt][nt][3]);
        }
    }
}

// ---------------------------------------------------------------------------
__global__ void tohalf_k(const float4* __restrict__ in, __half2* __restrict__ o, long n4)
{
    long i = (long)blockIdx.x * blockDim.x + threadIdx.x;
    const long stride = (long)gridDim.x * blockDim.x;
    for (; i < n4; i += stride) {
        float4 v = in[i];
        o[2 * i]     = __floats2half2_rn(v.x, v.y);
        o[2 * i + 1] = __floats2half2_rn(v.z, v.w);
    }
}

// ---------------------------------------------------------------------------
// Attention middle (tensor-core phases): one CTA per (n,t), warp = head.
// smem bytes: QS/VS [8][32x72]h @0 (36864) | KS @36864 | PRL f32 [8][625]
// @73728 (20000) | PRH f16 [8][32x40] @93728 (20480). Total 114208 -> 2 CTA/SM.
// Phase1: logits = Q@K^T via mma (A: QS non-trans x4; B: KS[j][d] non-trans x4).
// Softmax over heads in fp32 (ex2.approx, log2e pre-folded), probs -> PRH f16.
// Phase3: out = P@V via mma (A: PRH x4; B: VS x4.trans).
// ---------------------------------------------------------------------------
#define HQS   2304            // halves per head tile (32*72)
#define KS_B  36864
#define PRL_B 73728
#define PRH_B 93728
#define ATTN_SMEM 114208
#define LSCALE 0.1803368801f  // 0.125 * log2(e)

__global__ __launch_bounds__(256, 2)
void attn_kernel(const float* __restrict__ qkv, __half* __restrict__ att)
{
    extern __shared__ char smc[];
    __half* QS  = (__half*)(smc);
    __half* KSh = (__half*)(smc + KS_B);
    float*  PRL = (float*) (smc + PRL_B);
    __half* PRH = (__half*)(smc + PRH_B);
    const uint32_t sb = smem_u32(smc);

    const int b  = blockIdx.x;
    const int n  = b >> 8;
    const int ti = b & 255;
    const float* src = qkv + (long)n * QROWS * MCOL + ti * VV;
    const int tid = threadIdx.x;
    const int wid = tid >> 5, lane = tid & 31;
    const int g = lane >> 2, tg = lane & 3;
    const int l15 = lane & 15, lhi = lane >> 4;
    const int l7 = lane & 7, l8b = (lane >> 3) & 1;

    // Pre-zero PRH (pad rows/cols must be exact zero for phase3 A)
    for (int idx = tid; idx < 5120; idx += 256)
        ((uint32_t*)(smc + PRH_B))[idx] = 0;

    // Stage Q,K fp32->fp16 transposed: row r (c-idx) -> QS[h][token l][d]
    #pragma unroll 4
    for (int idx = tid; idx < 512 * 32; idx += 256) {
        const int r = idx >> 5, l = idx & 31;
        if (l < VV) {
            const float qv_ = src[(long)r * MCOL + l];
            const float kv_ = src[(long)(r + 512) * MCOL + l];
            const int off = (r >> 6) * HQS + l * 72 + (r & 63);
            QS[off]  = __float2half_rn(qv_);
            KSh[off] = __float2half_rn(kv_);
        }
    }
    __syncthreads();

    // Phase 1: per-warp head mma, D = Q@K^T
    {
        const uint32_t qb = sb + wid * (HQS * 2);
        const uint32_t kb = sb + KS_B + wid * (HQS * 2);
        float acc[2][4][4];
        #pragma unroll
        for (int i = 0; i < 2; i++)
            #pragma unroll
            for (int j = 0; j < 4; j++)
                #pragma unroll
                for (int q = 0; q < 4; q++) acc[i][j][q] = 0.f;
        #pragma unroll
        for (int kk = 0; kk < 4; kk++) {
            uint32_t af[2][4], bf[4][2];
            #pragma unroll
            for (int mt = 0; mt < 2; mt++)
                LDMX4(af[mt], qb + (mt * 16 + l15) * 144 + (kk * 16 + lhi * 8) * 2);
            #pragma unroll
            for (int p = 0; p < 2; p++)
                LDMX4T(bf[2 * p][0], bf[2 * p][1], bf[2 * p + 1][0], bf[2 * p + 1][1],
                       kb + 0);  // placeholder (replaced below)
            // NOTE: B frags are NON-trans loads from KS[j][d]; redo properly:
            #pragma unroll
            for (int p = 0; p < 2; p++) {
                uint32_t r4[4];
                LDMX4(r4, kb + (l7 + lhi * 8 + p * 16) * 144 + (kk * 16 + l8b * 8) * 2);
                bf[2 * p][0] = r4[0]; bf[2 * p][1] = r4[1];
                bf[2 * p + 1][0] = r4[2]; bf[2 * p + 1][1] = r4[3];
            }
            #pragma unroll
            for (int mt = 0; mt < 2; mt++)
                #pragma unroll
                for (int nt = 0; nt < 4; nt++)
                    mma_f16(acc[mt][nt], af[mt], bf[nt]);
        }
        // Store logits (scaled for exp2) to PRL fp32, guarded to 25x25
        float* prl = PRL + wid * 625;
        #pragma unroll
        for (int mt = 0; mt < 2; mt++) {
            #pragma unroll
            for (int nt = 0; nt < 4; nt++) {
                const int i0 = mt * 16 + g, j0 = nt * 8 + 2 * tg;
                if (j0 < VV) {
                    if (i0 < VV)     prl[i0 * 25 + j0]       = acc[mt][nt][0] * LSCALE;
                    if (i0 + 8 < VV) prl[(i0 + 8) * 25 + j0] = acc[mt][nt][2] * LSCALE;
                }
                if (j0 + 1 < VV) {
                    if (i0 < VV)     prl[i0 * 25 + j0 + 1]       = acc[mt][nt][1] * LSCALE;
                    if (i0 + 8 < VV) prl[(i0 + 8) * 25 + j0 + 1] = acc[mt][nt][3] * LSCALE;
                }
            }
        }
    }
    __syncthreads();

    // Phase 2: softmax over heads (fp32, ex2.approx) -> PRH fp16
    for (int idx = tid; idx < 800; idx += 256) {
        const int i = idx >> 5, j = idx & 31;
        if (j < VV) {
            float v[HEADS];
            #pragma unroll
            for (int hh = 0; hh < HEADS; hh++) v[hh] = PRL[hh * 625 + i * 25 + j];
            float m = v[0];
            #pragma unroll
            for (int hh = 1; hh < HEADS; hh++) m = fmaxf(m, v[hh]);
            float ssum = 0.f;
            #pragma unroll
            for (int hh = 0; hh < HEADS; hh++) {
                float e;
                asm("ex2.approx.f32 %0, %1;" : "=f"(e) : "f"(v[hh] - m));
                v[hh] = e; ssum += e;
            }
            float inv;
            asm("rcp.approx.f32 %0, %1;" : "=f"(inv) : "f"(ssum));
            #pragma unroll
            for (int hh = 0; hh < HEADS; hh++)
                PRH[hh * 1280 + i * 40 + j] = __float2half_rn(v[hh] * inv);
        }
    }
    // Stage V into QS region (fp16, transposed)
    #pragma unroll 4
    for (int idx = tid; idx < 512 * 32; idx += 256) {
        const int r = idx >> 5, l = idx & 31;
        if (l < VV)
            QS[(r >> 6) * HQS + l * 72 + (r & 63)] =
                __float2half_rn(src[(long)(r + 1024) * MCOL + l]);
    }
    // Zero V pad rows (tokens 25..31) per head
    if (tid < 56) {
        uint32_t* pz = (uint32_t*)(smc) + ((tid / 7) * HQS + (25 + tid % 7) * 72) / 2;
        #pragma unroll
        for (int c = 0; c < 36; c++) pz[c] = 0;
    }
    __syncthreads();

    // Phase 3: out = P@V per warp head
    {
        const uint32_t pb = sb + PRH_B + wid * 2560;
        const uint32_t vb = sb + wid * (HQS * 2);
        float acc2[2][8][4];
        #pragma unroll
        for (int i = 0; i < 2; i++)
            #pragma unroll
            for (int j = 0; j < 8; j++)
                #pragma unroll
                for (int q = 0; q < 4; q++) acc2[i][j][q] = 0.f;
        const int bkrow = l7 + l8b * 8, bcoff = lhi * 8;
        #pragma unroll
        for (int kk = 0; kk < 2; kk++) {
            uint32_t af[2][4], bf[8][2];
            #pragma unroll
            for (int mt = 0; mt < 2; mt++)
                LDMX4(af[mt], pb + (mt * 16 + l15) * 80 + (kk * 16 + lhi * 8) * 2);
            #pragma unroll
            for (int p = 0; p < 4; p++)
                LDMX4T(bf[2 * p][0], bf[2 * p][1], bf[2 * p + 1][0], bf[2 * p + 1][1],
                       vb + (kk * 16 + bkrow) * 144 + (p * 16 + bcoff) * 2);
            #pragma unroll
            for (int mt = 0; mt < 2; mt++)
                #pragma unroll
                for (int nt = 0; nt < 8; nt++)
                    mma_f16(acc2[mt][nt], af[mt], bf[nt]);
        }
        // Store out fp16 to att[(h*64+d)*MCOL + ti*25 + i]
        __half* dst = att + (long)n * CDIM * MCOL + ti * VV;
        #pragma unroll
        for (int mt = 0; mt < 2; mt++) {
            #pragma unroll
            for (int nt = 0; nt < 8; nt++) {
                const int i0 = mt * 16 + g, d0 = nt * 8 + 2 * tg;
                const long c0 = (long)(wid * HD + d0) * MCOL;
                const long c1 = (long)(wid * HD + d0 + 1) * MCOL;
                if (i0 < VV) {
                    dst[c0 + i0] = __float2half_rn(acc2[mt][nt][0]);
                    dst[c1 + i0] = __float2half_rn(acc2[mt][nt][1]);
                }
                if (i0 + 8 < VV) {
                    dst[c0 + i0 + 8] = __float2half_rn(acc2[mt][nt][2]);
                    dst[c1 + i0 + 8] = __float2half_rn(acc2[mt][nt][3]);
                }
            }
        }
    }
}

// ---------------------------------------------------------------------------
extern "C" void kernel_launch(void* const* d_in, const int* in_sizes, int n_in,
                              void* d_out, int out_size)
{
    const float* x     = (const float*)d_in[0];
    const float* wqkv  = (const float*)d_in[1];
    const float* wproj = (const float*)d_in[2];
    float* out = (float*)d_out;

    float  *qkv;
    __half *att, *x16, *wq16, *wp16;
    cudaGetSymbolAddress((void**)&qkv,  g_qkv);
    cudaGetSymbolAddress((void**)&att,  g_att);
    cudaGetSymbolAddress((void**)&x16,  g_x16);
    cudaGetSymbolAddress((void**)&wq16, g_wq16);
    cudaGetSymbolAddress((void**)&wp16, g_wp16);

    cudaFuncSetAttribute((const void*)h16_gemm,
                         cudaFuncAttributeMaxDynamicSharedMemorySize, SMEM_G);
    cudaFuncSetAttribute((const void*)attn_kernel,
                         cudaFuncAttributeMaxDynamicSharedMemorySize, ATTN_SMEM);

    tohalf_k<<<4096, 256>>>((const float4*)x,     (__half2*)x16,  (long)NB * CDIM * MCOL / 4);
    tohalf_k<<<512,  256>>>((const float4*)wqkv,  (__half2*)wq16, (long)QROWS * CDIM / 4);
    tohalf_k<<<512,  256>>>((const float4*)wproj, (__half2*)wp16, (long)CDIM * CDIM / 4);

    // QKV: per-n [1536,6400] = W_qkv[1536,512] @ X_n[512,6400]
    h16_gemm<<<dim3(MCOL / BNT, QROWS / BMT, NB), 256, SMEM_G>>>(
        wq16, x16, qkv, MCOL, (long)CDIM * MCOL, (long)QROWS * MCOL);

    attn_kernel<<<dim3(NB * TDIM), 256, ATTN_SMEM>>>(qkv, att);

    // Proj: per-n [512,6400] = W_proj[512,512] @ O_n[512,6400]
    h16_gemm<<<dim3(MCOL / BNT, CDIM / BMT, NB), 256, SMEM_G>>>(
        wp16, att, out, MCOL, (long)CDIM * MCOL, (long)CDIM * MCOL);
}

// round 16
// speedup vs baseline: 1.4647x; 1.0404x over previous
#include <cuda_runtime.h>
#include <cuda_fp16.h>
#include <cstdint>
#include <math.h>

// Problem constants
#define NB    16
#define CDIM  512
#define TDIM  256
#define VV    25
#define HEADS 8
#define HD    64
#define MCOL  6400
#define QROWS 1536

// Scratch (__device__ globals per allocation-free rule)
__device__ __half g_qkv[(size_t)NB * QROWS * MCOL];   // QKV output (fp16)
__device__ __half g_att[(size_t)NB * CDIM * MCOL];    // attn output (fp16)
__device__ __half g_x16[(size_t)NB * CDIM * MCOL];    // x -> fp16
__device__ __half g_wq16[QROWS * CDIM];               // w_qkv -> fp16
__device__ __half g_wp16[CDIM * CDIM];                // w_proj -> fp16

// ---------------------------------------------------------------------------
__device__ __forceinline__ uint32_t smem_u32(const void* p) {
    uint32_t a;
    asm("{ .reg .u64 t; cvta.to.shared.u64 t, %1; cvt.u32.u64 %0, t; }" : "=r"(a) : "l"(p));
    return a;
}
__device__ __forceinline__ void mma_f16(float* c, const uint32_t* a, const uint32_t* b) {
    asm volatile(
        "mma.sync.aligned.m16n8k16.row.col.f32.f16.f16.f32 "
        "{%0,%1,%2,%3}, {%4,%5,%6,%7}, {%8,%9}, {%0,%1,%2,%3};"
        : "+f"(c[0]), "+f"(c[1]), "+f"(c[2]), "+f"(c[3])
        : "r"(a[0]), "r"(a[1]), "r"(a[2]), "r"(a[3]), "r"(b[0]), "r"(b[1]));
}
#define CP16(dst, src) \
    asm volatile("cp.async.cg.shared.global [%0], [%1], 16;" :: "r"(dst), "l"(src))
#define CP_COMMIT() asm volatile("cp.async.commit_group;" ::: "memory")
#define LDMX4(r, ad) \
    asm volatile("ldmatrix.sync.aligned.m8n8.x4.shared.b16 {%0,%1,%2,%3}, [%4];" \
        : "=r"((r)[0]), "=r"((r)[1]), "=r"((r)[2]), "=r"((r)[3]) : "r"(ad))
#define LDMX4T(r0, r1, r2, r3, ad) \
    asm volatile("ldmatrix.sync.aligned.m8n8.x4.trans.shared.b16 {%0,%1,%2,%3}, [%4];" \
        : "=r"(r0), "=r"(r1), "=r"(r2), "=r"(r3) : "r"(ad))

// ---------------------------------------------------------------------------
// fp16 GEMM (R13/R15 config): CTA 128x128, 8 warps (2m x 4n) 64x32, KT=32,
// 4-stage cp.async, 2 CTAs/SM. HALF_OUT selects fp16 vs fp32 C store.
// ---------------------------------------------------------------------------
#define BMT 128
#define BNT 128
#define KT  32
#define NSTAGE 4
#define A_STB  (128 * 64)
#define BROW   272
#define B_STB  (32 * BROW)
#define B_OFF  (NSTAGE * A_STB)
#define SMEM_G (B_OFF + NSTAGE * B_STB)   // 67584

template <bool HALF_OUT>
__global__ __launch_bounds__(256, 2)
void h16_gemm(const __half* __restrict__ A, const __half* __restrict__ B,
              void* __restrict__ Cv, int Nld, long sB, long sC)
{
    extern __shared__ char sm[];
    const uint32_t sbase = smem_u32(sm);
    B += (long)blockIdx.z * sB;
    const int bm = blockIdx.y * BMT;
    const int bn = blockIdx.x * BNT;

    const int tid  = threadIdx.x;
    const int wid  = tid >> 5, lane = tid & 31;
    const int g    = lane >> 2, tg = lane & 3;
    const int wm   = (wid & 1) * 64, wn = (wid >> 1) * 32;

    const int am = tid >> 1, ac = tid & 1;
    const __half* Ag = A + (long)(bm + am) * CDIM + ac * 16;
    const uint32_t am_sw = (uint32_t)((am >> 1) & 3);
    const int bk = tid >> 3, bc = tid & 7;
    const __half* Bg = B + (long)bk * Nld + bn + bc * 8;
    const uint32_t b_soff = (uint32_t)(bk * BROW + bc * 16);

    const int arow  = lane & 15;
    const int achk  = lane >> 4;
    const int bkrow = (lane & 7) + ((lane >> 3) & 1) * 8;
    const int bcoff = ((lane >> 4) & 1) * 8;

    float acc[4][4][4];
    #pragma unroll
    for (int i = 0; i < 4; i++)
        #pragma unroll
        for (int j = 0; j < 4; j++)
            #pragma unroll
            for (int q = 0; q < 4; q++) acc[i][j][q] = 0.f;

    auto issue = [&](int s) {
        const int st = s & (NSTAGE - 1);
        const uint32_t ab = sbase + st * A_STB + am * 64;
        const __half* ag = Ag + s * KT;
        #pragma unroll
        for (int j = 0; j < 2; j++)
            CP16(ab + (((uint32_t)(2 * ac + j)) ^ am_sw) * 16, ag + j * 8);
        const uint32_t bb = sbase + B_OFF + st * B_STB + b_soff;
        const __half* bg = Bg + (long)s * KT * Nld;
        CP16(bb, bg);
        CP16(bb + 128, bg + 64);
    };

    issue(0); CP_COMMIT();
    issue(1); CP_COMMIT();
    issue(2); CP_COMMIT();

    const int NIT = CDIM / KT;
    for (int s = 0; s < NIT; s++) {
        asm volatile("cp.async.wait_group 2;" ::: "memory");
        __syncthreads();
        if (s + 3 < NIT) issue(s + 3);
        CP_COMMIT();

        const int st = s & (NSTAGE - 1);
        const uint32_t ab = sbase + st * A_STB;
        const uint32_t bb = sbase + B_OFF + st * B_STB;
        #pragma unroll
        for (int ks = 0; ks < 2; ks++) {
            uint32_t af[4][4];
            #pragma unroll
            for (int mt = 0; mt < 4; mt++) {
                const int ml = wm + mt * 16 + arow;
                const uint32_t ad = ab + ml * 64 +
                    (((uint32_t)(ks * 2 + achk)) ^ ((uint32_t)((ml >> 1) & 3))) * 16;
                LDMX4(af[mt], ad);
            }
            uint32_t bf[4][2];
            #pragma unroll
            for (int ntp = 0; ntp < 2; ntp++) {
                const uint32_t bd = bb + (ks * 16 + bkrow) * BROW +
                                    (wn + ntp * 16 + bcoff) * 2;
                LDMX4T(bf[2 * ntp][0], bf[2 * ntp][1],
                       bf[2 * ntp + 1][0], bf[2 * ntp + 1][1], bd);
            }
            #pragma unroll
            for (int mt = 0; mt < 4; mt++)
                #pragma unroll
                for (int nt = 0; nt < 4; nt++)
                    mma_f16(acc[mt][nt], af[mt], bf[nt]);
        }
    }

    if (HALF_OUT) {
        __half* C = (__half*)Cv + (long)blockIdx.z * sC;
        #pragma unroll
        for (int mt = 0; mt < 4; mt++) {
            #pragma unroll
            for (int nt = 0; nt < 4; nt++) {
                const long r0 = bm + wm + mt * 16 + g;
                const int  cc = bn + wn + nt * 8 + 2 * tg;
                *(__half2*)(C + r0 * Nld + cc) =
                    __floats2half2_rn(acc[mt][nt][0], acc[mt][nt][1]);
                *(__half2*)(C + (r0 + 8) * Nld + cc) =
                    __floats2half2_rn(acc[mt][nt][2], acc[mt][nt][3]);
            }
        }
    } else {
        float* C = (float*)Cv + (long)blockIdx.z * sC;
        #pragma unroll
        for (int mt = 0; mt < 4; mt++) {
            #pragma unroll
            for (int nt = 0; nt < 4; nt++) {
                const long r0 = bm + wm + mt * 16 + g;
                const int  cc = bn + wn + nt * 8 + 2 * tg;
                *(float2*)(C + r0 * Nld + cc)       = make_float2(acc[mt][nt][0], acc[mt][nt][1]);
                *(float2*)(C + (r0 + 8) * Nld + cc) = make_float2(acc[mt][nt][2], acc[mt][nt][3]);
            }
        }
    }
}

// ---------------------------------------------------------------------------
__global__ void tohalf_k(const float4* __restrict__ in, __half2* __restrict__ o, long n4)
{
    long i = (long)blockIdx.x * blockDim.x + threadIdx.x;
    const long stride = (long)gridDim.x * blockDim.x;
    for (; i < n4; i += stride) {
        float4 v = in[i];
        o[2 * i]     = __floats2half2_rn(v.x, v.y);
        o[2 * i + 1] = __floats2half2_rn(v.z, v.w);
    }
}

// ---------------------------------------------------------------------------
// Attention middle (tensor-core phases): one CTA per (n,t), warp = head.
// qkv is fp16 now: staging = direct half copies.
// smem: QS/VS [8][32x72]h @0 | KS @36864 | PRL f32 @73728 | PRH f16 @93728.
// ---------------------------------------------------------------------------
#define HQS   2304            // halves per head tile (32*72)
#define KS_B  36864
#define PRL_B 73728
#define PRH_B 93728
#define ATTN_SMEM 114208
#define LSCALE 0.1803368801f  // 0.125 * log2(e)

__global__ __launch_bounds__(256, 2)
void attn_kernel(const __half* __restrict__ qkv, __half* __restrict__ att)
{
    extern __shared__ char smc[];
    __half* QS  = (__half*)(smc);
    __half* KSh = (__half*)(smc + KS_B);
    float*  PRL = (float*) (smc + PRL_B);
    __half* PRH = (__half*)(smc + PRH_B);
    const uint32_t sb = smem_u32(smc);

    const int b  = blockIdx.x;
    const int n  = b >> 8;
    const int ti = b & 255;
    const __half* src = qkv + (long)n * QROWS * MCOL + ti * VV;
    const int tid = threadIdx.x;
    const int wid = tid >> 5, lane = tid & 31;
    const int g = lane >> 2, tg = lane & 3;
    const int l15 = lane & 15, lhi = lane >> 4;
    const int l7 = lane & 7, l8b = (lane >> 3) & 1;

    // Pre-zero PRH (pad rows/cols must be exact zero for phase3 A)
    for (int idx = tid; idx < 5120; idx += 256)
        ((uint32_t*)(smc + PRH_B))[idx] = 0;

    // Stage Q,K (fp16 direct): row r (c-idx) -> QS[h][token l][d]
    #pragma unroll 4
    for (int idx = tid; idx < 512 * 32; idx += 256) {
        const int r = idx >> 5, l = idx & 31;
        if (l < VV) {
            const int off = (r >> 6) * HQS + l * 72 + (r & 63);
            QS[off]  = src[(long)r * MCOL + l];
            KSh[off] = src[(long)(r + 512) * MCOL + l];
        }
    }
    __syncthreads();

    // Phase 1: per-warp head mma, D = Q@K^T
    {
        const uint32_t qb = sb + wid * (HQS * 2);
        const uint32_t kb = sb + KS_B + wid * (HQS * 2);
        float acc[2][4][4];
        #pragma unroll
        for (int i = 0; i < 2; i++)
            #pragma unroll
            for (int j = 0; j < 4; j++)
                #pragma unroll
                for (int q = 0; q < 4; q++) acc[i][j][q] = 0.f;
        #pragma unroll
        for (int kk = 0; kk < 4; kk++) {
            uint32_t af[2][4], bf[4][2];
            #pragma unroll
            for (int mt = 0; mt < 2; mt++)
                LDMX4(af[mt], qb + (mt * 16 + l15) * 144 + (kk * 16 + lhi * 8) * 2);
            #pragma unroll
            for (int p = 0; p < 2; p++) {
                uint32_t r4[4];
                LDMX4(r4, kb + (l7 + lhi * 8 + p * 16) * 144 + (kk * 16 + l8b * 8) * 2);
                bf[2 * p][0] = r4[0]; bf[2 * p][1] = r4[1];
                bf[2 * p + 1][0] = r4[2]; bf[2 * p + 1][1] = r4[3];
            }
            #pragma unroll
            for (int mt = 0; mt < 2; mt++)
                #pragma unroll
                for (int nt = 0; nt < 4; nt++)
                    mma_f16(acc[mt][nt], af[mt], bf[nt]);
        }
        // Store logits (scaled for exp2) to PRL fp32, guarded to 25x25
        float* prl = PRL + wid * 625;
        #pragma unroll
        for (int mt = 0; mt < 2; mt++) {
            #pragma unroll
            for (int nt = 0; nt < 4; nt++) {
                const int i0 = mt * 16 + g, j0 = nt * 8 + 2 * tg;
                if (j0 < VV) {
                    if (i0 < VV)     prl[i0 * 25 + j0]       = acc[mt][nt][0] * LSCALE;
                    if (i0 + 8 < VV) prl[(i0 + 8) * 25 + j0] = acc[mt][nt][2] * LSCALE;
                }
                if (j0 + 1 < VV) {
                    if (i0 < VV)     prl[i0 * 25 + j0 + 1]       = acc[mt][nt][1] * LSCALE;
                    if (i0 + 8 < VV) prl[(i0 + 8) * 25 + j0 + 1] = acc[mt][nt][3] * LSCALE;
                }
            }
        }
    }
    __syncthreads();

    // Phase 2: softmax over heads (fp32, ex2.approx) -> PRH fp16
    for (int idx = tid; idx < 800; idx += 256) {
        const int i = idx >> 5, j = idx & 31;
        if (j < VV) {
            float v[HEADS];
            #pragma unroll
            for (int hh = 0; hh < HEADS; hh++) v[hh] = PRL[hh * 625 + i * 25 + j];
            float m = v[0];
            #pragma unroll
            for (int hh = 1; hh < HEADS; hh++) m = fmaxf(m, v[hh]);
            float ssum = 0.f;
            #pragma unroll
            for (int hh = 0; hh < HEADS; hh++) {
                float e;
                asm("ex2.approx.f32 %0, %1;" : "=f"(e) : "f"(v[hh] - m));
                v[hh] = e; ssum += e;
            }
            float inv;
            asm("rcp.approx.f32 %0, %1;" : "=f"(inv) : "f"(ssum));
            #pragma unroll
            for (int hh = 0; hh < HEADS; hh++)
                PRH[hh * 1280 + i * 40 + j] = __float2half_rn(v[hh] * inv);
        }
    }
    // Stage V into QS region (fp16 direct, transposed)
    #pragma unroll 4
    for (int idx = tid; idx < 512 * 32; idx += 256) {
        const int r = idx >> 5, l = idx & 31;
        if (l < VV)
            QS[(r >> 6) * HQS + l * 72 + (r & 63)] = src[(long)(r + 1024) * MCOL + l];
    }
    // Zero V pad rows (tokens 25..31) per head
    if (tid < 56) {
        uint32_t* pz = (uint32_t*)(smc) + ((tid / 7) * HQS + (25 + tid % 7) * 72) / 2;
        #pragma unroll
        for (int c = 0; c < 36; c++) pz[c] = 0;
    }
    __syncthreads();

    // Phase 3: out = P@V per warp head
    {
        const uint32_t pb = sb + PRH_B + wid * 2560;
        const uint32_t vb = sb + wid * (HQS * 2);
        float acc2[2][8][4];
        #pragma unroll
        for (int i = 0; i < 2; i++)
            #pragma unroll
            for (int j = 0; j < 8; j++)
                #pragma unroll
                for (int q = 0; q < 4; q++) acc2[i][j][q] = 0.f;
        const int bkrow = l7 + l8b * 8, bcoff = lhi * 8;
        #pragma unroll
        for (int kk = 0; kk < 2; kk++) {
            uint32_t af[2][4], bf[8][2];
            #pragma unroll
            for (int mt = 0; mt < 2; mt++)
                LDMX4(af[mt], pb + (mt * 16 + l15) * 80 + (kk * 16 + lhi * 8) * 2);
            #pragma unroll
            for (int p = 0; p < 4; p++)
                LDMX4T(bf[2 * p][0], bf[2 * p][1], bf[2 * p + 1][0], bf[2 * p + 1][1],
                       vb + (kk * 16 + bkrow) * 144 + (p * 16 + bcoff) * 2);
            #pragma unroll
            for (int mt = 0; mt < 2; mt++)
                #pragma unroll
                for (int nt = 0; nt < 8; nt++)
                    mma_f16(acc2[mt][nt], af[mt], bf[nt]);
        }
        // Store out fp16 to att[(h*64+d)*MCOL + ti*25 + i]
        __half* dst = att + (long)n * CDIM * MCOL + ti * VV;
        #pragma unroll
        for (int mt = 0; mt < 2; mt++) {
            #pragma unroll
            for (int nt = 0; nt < 8; nt++) {
                const int i0 = mt * 16 + g, d0 = nt * 8 + 2 * tg;
                const long c0 = (long)(wid * HD + d0) * MCOL;
                const long c1 = (long)(wid * HD + d0 + 1) * MCOL;
                if (i0 < VV) {
                    dst[c0 + i0] = __float2half_rn(acc2[mt][nt][0]);
                    dst[c1 + i0] = __float2half_rn(acc2[mt][nt][1]);
                }
                if (i0 + 8 < VV) {
                    dst[c0 + i0 + 8] = __float2half_rn(acc2[mt][nt][2]);
                    dst[c1 + i0 + 8] = __float2half_rn(acc2[mt][nt][3]);
                }
            }
        }
    }
}

// ---------------------------------------------------------------------------
extern "C" void kernel_launch(void* const* d_in, const int* in_sizes, int n_in,
                              void* d_out, int out_size)
{
    const float* x     = (const float*)d_in[0];
    const float* wqkv  = (const float*)d_in[1];
    const float* wproj = (const float*)d_in[2];
    float* out = (float*)d_out;

    __half *qkv, *att, *x16, *wq16, *wp16;
    cudaGetSymbolAddress((void**)&qkv,  g_qkv);
    cudaGetSymbolAddress((void**)&att,  g_att);
    cudaGetSymbolAddress((void**)&x16,  g_x16);
    cudaGetSymbolAddress((void**)&wq16, g_wq16);
    cudaGetSymbolAddress((void**)&wp16, g_wp16);

    cudaFuncSetAttribute((const void*)h16_gemm<true>,
                         cudaFuncAttributeMaxDynamicSharedMemorySize, SMEM_G);
    cudaFuncSetAttribute((const void*)h16_gemm<false>,
                         cudaFuncAttributeMaxDynamicSharedMemorySize, SMEM_G);
    cudaFuncSetAttribute((const void*)attn_kernel,
                         cudaFuncAttributeMaxDynamicSharedMemorySize, ATTN_SMEM);

    tohalf_k<<<4096, 256>>>((const float4*)x,     (__half2*)x16,  (long)NB * CDIM * MCOL / 4);
    tohalf_k<<<512,  256>>>((const float4*)wqkv,  (__half2*)wq16, (long)QROWS * CDIM / 4);
    tohalf_k<<<512,  256>>>((const float4*)wproj, (__half2*)wp16, (long)CDIM * CDIM / 4);

    // QKV: per-n [1536,6400] = W_qkv[1536,512] @ X_n[512,6400] -> fp16
    h16_gemm<true><<<dim3(MCOL / BNT, QROWS / BMT, NB), 256, SMEM_G>>>(
        wq16, x16, qkv, MCOL, (long)CDIM * MCOL, (long)QROWS * MCOL);

    attn_kernel<<<dim3(NB * TDIM), 256, ATTN_SMEM>>>(qkv, att);

    // Proj: per-n [512,6400] = W_proj[512,512] @ O_n[512,6400] -> fp32 out
    h16_gemm<false><<<dim3(MCOL / BNT, CDIM / BMT, NB), 256, SMEM_G>>>(
        wp16, att, out, MCOL, (long)CDIM * MCOL, (long)CDIM * MCOL);
}